// round 9
// baseline (speedup 1.0000x reference)
#include <cuda_runtime.h>
#include <math.h>

#define Sn 512
#define Bn 128
#define En 300
#define KP 304          // padded K for GEMM
#define Hn 256
#define Nc 2048         // combined gate width (fwd 1024 | bwd 1024)
#define Cn 6
#define Pn 256
#define H2 512
#define G3 1536

typedef unsigned long long ull;

// ---------------- f32x2 helpers ---------------------------------------------
__device__ __forceinline__ ull fma2(ull a, ull b, ull c) {
    ull d; asm("fma.rn.f32x2 %0, %1, %2, %3;" : "=l"(d) : "l"(a), "l"(b), "l"(c));
    return d;
}
__device__ __forceinline__ ull pack2(float x, float y) {
    ull d; asm("mov.b64 %0, {%1, %2};" : "=l"(d) : "f"(x), "f"(y));
    return d;
}
__device__ __forceinline__ float2 unpack2(ull p) {
    float2 r; asm("mov.b64 {%0, %1}, %2;" : "=f"(r.x), "=f"(r.y) : "l"(p));
    return r;
}
__device__ __forceinline__ float sigf(float x) { return 1.f / (1.f + __expf(-x)); }
__device__ __forceinline__ unsigned s2u(const void* p) {
    return (unsigned)__cvta_generic_to_shared(p);
}

// ---------------- scratch (static; no cudaMalloc) ---------------------------
__device__ float g_emb[Sn * Bn * KP];          // [S*B][304] zero-padded
__device__ float g_gx[(size_t)Sn * Bn * Nc];   // [S*B][2048] fwd|bwd gates
__device__ float g_Wc[Nc * KP];                // combined padded Wih
__device__ float g_bc[Nc];                     // combined bih+bhh
__device__ float g_hbuf[2 * Bn * Hn];          // final h: [dir][b][h]
__device__ float g_hdec[2][Bn * H2];
__device__ float g_gxd[Cn * G3];
__device__ float g_dT[H2 * G3];
__device__ float g_pT[H2 * Pn];

// ---------------- embedding: g_emb[s*128+b][0:300] = tanh(embed_W[tok]) -----
__global__ void embed_kernel(const int* __restrict__ seq,
                             const float* __restrict__ embW) {
    int m = blockIdx.x;              // m = s*128 + b
    int s = m >> 7, b = m & 127;
    int tok = seq[b * Sn + s];
    const float* src = embW + (size_t)tok * En;
    float* dst = g_emb + (size_t)m * KP;
    for (int e = threadIdx.x; e < En; e += blockDim.x)
        dst[e] = tanhf(src[e]);
    for (int e = En + threadIdx.x; e < KP; e += blockDim.x)
        dst[e] = 0.f;
}

// ---------------- build combined padded weights + bias ----------------------
__global__ void prep_w(const float* __restrict__ fWih, const float* __restrict__ bWih,
                       const float* __restrict__ fbih, const float* __restrict__ fbhh,
                       const float* __restrict__ bbih, const float* __restrict__ bbhh) {
    int i = blockIdx.x * blockDim.x + threadIdx.x;
    if (i < Nc * KP) {
        int n = i / KP, e = i - n * KP;
        float v = 0.f;
        if (e < En) v = (n < 1024) ? fWih[n * En + e] : bWih[(n - 1024) * En + e];
        g_Wc[i] = v;
    }
    if (i < Nc)
        g_bc[i] = (i < 1024) ? (fbih[i] + fbhh[i]) : (bbih[i - 1024] + bbhh[i - 1024]);
}

// ---------------- f32x2 SGEMM v3: C[M,2048] = A[M,304]*W[2048,304]^T + bias --
// N-pairs packed in f32x2 lanes (natural W loads, no inner-loop packs);
// A pre-duplicated (a,a) in smem at fill time (broadcast loads).
// BM=BN=128, BK=16, 256 threads, 8m x 8n per thread, double-buffered.
#define ADS 130   // A-dup row stride (ull)
#define WSS 132   // W row stride (float)
__global__ void __launch_bounds__(256, 2)
sgemm3(const float* __restrict__ A, const float* __restrict__ W,
       const float* __restrict__ bias, float* __restrict__ C) {
    extern __shared__ ull dynsm[];
    ull* Ad = dynsm;                          // [2][16][ADS] dup-packed
    float* Wsf = (float*)(dynsm + 2 * 16 * ADS);  // [2][16][WSS]
    int bm = blockIdx.y * 128, bn = blockIdx.x * 128;
    int t = threadIdx.x;
    int tx = t & 15, ty = t >> 4;
    int row = t >> 1;                 // 0..127
    int kc = (t & 1) * 8;             // 0 or 8
    const float* Ap = A + (size_t)(bm + row) * KP + kc;
    const float* Wp = W + (size_t)(bn + row) * KP + kc;

    ull acc[8][4];
#pragma unroll
    for (int i = 0; i < 8; i++)
#pragma unroll
        for (int j = 0; j < 4; j++) acc[i][j] = 0ull;

    float4 a0 = *(const float4*)(Ap);
    float4 a1 = *(const float4*)(Ap + 4);
    float4 w0 = *(const float4*)(Wp);
    float4 w1 = *(const float4*)(Wp + 4);
    {
        ull* ad = Ad; float* ws = Wsf;
        ad[(kc + 0) * ADS + row] = pack2(a0.x, a0.x);
        ad[(kc + 1) * ADS + row] = pack2(a0.y, a0.y);
        ad[(kc + 2) * ADS + row] = pack2(a0.z, a0.z);
        ad[(kc + 3) * ADS + row] = pack2(a0.w, a0.w);
        ad[(kc + 4) * ADS + row] = pack2(a1.x, a1.x);
        ad[(kc + 5) * ADS + row] = pack2(a1.y, a1.y);
        ad[(kc + 6) * ADS + row] = pack2(a1.z, a1.z);
        ad[(kc + 7) * ADS + row] = pack2(a1.w, a1.w);
        ws[(kc + 0) * WSS + row] = w0.x; ws[(kc + 1) * WSS + row] = w0.y;
        ws[(kc + 2) * WSS + row] = w0.z; ws[(kc + 3) * WSS + row] = w0.w;
        ws[(kc + 4) * WSS + row] = w1.x; ws[(kc + 5) * WSS + row] = w1.y;
        ws[(kc + 6) * WSS + row] = w1.z; ws[(kc + 7) * WSS + row] = w1.w;
    }
    __syncthreads();

#pragma unroll 1
    for (int it = 0; it < 19; it++) {
        int buf = it & 1;
        if (it < 18) {
            int k0 = (it + 1) * 16;
            a0 = *(const float4*)(Ap + k0);
            a1 = *(const float4*)(Ap + k0 + 4);
            w0 = *(const float4*)(Wp + k0);
            w1 = *(const float4*)(Wp + k0 + 4);
        }
        const ull* ad = Ad + buf * 16 * ADS;
        const float* ws = Wsf + buf * 16 * WSS;
#pragma unroll 4
        for (int kk = 0; kk < 16; kk++) {
            const ull* ap = ad + kk * ADS + ty * 8;
            ulonglong2 A01 = *(const ulonglong2*)(ap);
            ulonglong2 A23 = *(const ulonglong2*)(ap + 2);
            ulonglong2 A45 = *(const ulonglong2*)(ap + 4);
            ulonglong2 A67 = *(const ulonglong2*)(ap + 6);
            ull am[8] = {A01.x, A01.y, A23.x, A23.y, A45.x, A45.y, A67.x, A67.y};
            const ulonglong2* wp2 = (const ulonglong2*)(ws + kk * WSS + tx * 8);
            ulonglong2 W03 = wp2[0], W47 = wp2[1];
            ull wn[4] = {W03.x, W03.y, W47.x, W47.y};
#pragma unroll
            for (int mi = 0; mi < 8; mi++)
#pragma unroll
                for (int np = 0; np < 4; np++)
                    acc[mi][np] = fma2(am[mi], wn[np], acc[mi][np]);
        }
        if (it < 18) {
            ull* ad2 = Ad + (1 - buf) * 16 * ADS;
            float* ws2 = Wsf + (1 - buf) * 16 * WSS;
            ad2[(kc + 0) * ADS + row] = pack2(a0.x, a0.x);
            ad2[(kc + 1) * ADS + row] = pack2(a0.y, a0.y);
            ad2[(kc + 2) * ADS + row] = pack2(a0.z, a0.z);
            ad2[(kc + 3) * ADS + row] = pack2(a0.w, a0.w);
            ad2[(kc + 4) * ADS + row] = pack2(a1.x, a1.x);
            ad2[(kc + 5) * ADS + row] = pack2(a1.y, a1.y);
            ad2[(kc + 6) * ADS + row] = pack2(a1.z, a1.z);
            ad2[(kc + 7) * ADS + row] = pack2(a1.w, a1.w);
            ws2[(kc + 0) * WSS + row] = w0.x; ws2[(kc + 1) * WSS + row] = w0.y;
            ws2[(kc + 2) * WSS + row] = w0.z; ws2[(kc + 3) * WSS + row] = w0.w;
            ws2[(kc + 4) * WSS + row] = w1.x; ws2[(kc + 5) * WSS + row] = w1.y;
            ws2[(kc + 6) * WSS + row] = w1.z; ws2[(kc + 7) * WSS + row] = w1.w;
            __syncthreads();
        }
    }

    float4 bb0 = *(const float4*)(bias + bn + tx * 8);
    float4 bb1 = *(const float4*)(bias + bn + tx * 8 + 4);
#pragma unroll
    for (int mi = 0; mi < 8; mi++) {
        float2 p0 = unpack2(acc[mi][0]);
        float2 p1 = unpack2(acc[mi][1]);
        float2 p2 = unpack2(acc[mi][2]);
        float2 p3 = unpack2(acc[mi][3]);
        size_t r = (size_t)(bm + ty * 8 + mi);
        float4 o;
        o.x = p0.x + bb0.x; o.y = p0.y + bb0.y; o.z = p1.x + bb0.z; o.w = p1.y + bb0.w;
        *(float4*)(C + r * Nc + bn + tx * 8) = o;
        o.x = p2.x + bb1.x; o.y = p2.y + bb1.y; o.z = p3.x + bb1.z; o.w = p3.y + bb1.w;
        *(float4*)(C + r * Nc + bn + tx * 8 + 4) = o;
    }
}
#define SGEMM3_SMEM (2 * 16 * ADS * 8 + 2 * 16 * WSS * 4)   // 50176 B

// ---------------- persistent bidirectional LSTM recurrence (v3) -------------
// 128 CTAs in 16 clusters of 8. Cluster = {dir, batch-group}; CTA = 32-unit
// slice (uslot = cluster rank). Warp = batch pair, lane = unit. Gates packed
// (i,f)/(g,o) in f32x2; Wsm[k][u][g] read as one LDS.128 per k. h exchanged
// via DSMEM (st.shared::cluster to all 8 ranks) + HW cluster barrier.
__global__ void __launch_bounds__(256, 1) __cluster_dims__(8, 1, 1)
lstm3(const float* __restrict__ fWhh, const float* __restrict__ bWhh) {
    extern __shared__ float sm[];
    float* Wsm = sm;                       // [256 k][132] : [k][u*4+g]
    ull* hsm = (ull*)(sm + 256 * 132);     // [2 phase][256 k][9 pad] batch pairs

    int cb = blockIdx.x;
    int dir = cb >> 6;
    int L = cb & 63;
    int bg = L >> 3;
    int uslot = L & 7;                     // == cluster rank
    int u0 = uslot * 32;
    int b0 = bg * 16;
    const float* Whh = dir ? bWhh : fWhh;
    const float* gx = g_gx + dir * 1024;
    int t = threadIdx.x, w = t >> 5, u = t & 31;

    // Wsm[k*132 + uu*4 + g] = Whh[(g*256 + u0+uu)*256 + k]  (coalesced in k)
    for (int i = t; i < 32768; i += 256) {
        int k = i & 255, r = i >> 8;       // r: 0..127
        int uu = r >> 2, g = r & 3;
        Wsm[k * 132 + uu * 4 + g] = Whh[(size_t)(g * Hn + u0 + uu) * Hn + k];
    }
    // zero phase-0 h
    for (int i = t; i < 256 * 9; i += 256) hsm[i] = 0ull;
    __syncthreads();

    unsigned hbase = s2u(hsm);
    float2 cc = make_float2(0.f, 0.f);

    for (int s = 0; s < Sn; s++) {
        int p = s & 1;
        int xs = dir ? ((Sn - s) & (Sn - 1)) : s;
        // prefetch input gates for this thread's outputs (b0+2w, b0+2w+1)
        const float* gp = gx + ((size_t)xs * Bn + b0 + 2 * w) * Nc + u0 + u;
        float ga00 = gp[0], ga01 = gp[256], ga02 = gp[512], ga03 = gp[768];
        float ga10 = gp[Nc], ga11 = gp[Nc + 256], ga12 = gp[Nc + 512], ga13 = gp[Nc + 768];

        const ull* hrow = hsm + (size_t)p * 2304 + w;
        const float* wbase = Wsm + (u << 2);
        ull aif0 = 0ull, ago0 = 0ull, aif1 = 0ull, ago1 = 0ull;
#pragma unroll 8
        for (int k = 0; k < Hn; k++) {
            float2 hv = unpack2(hrow[k * 9]);          // broadcast LDS.64
            ull h0 = pack2(hv.x, hv.x);
            ull h1 = pack2(hv.y, hv.y);
            ulonglong2 wv = *(const ulonglong2*)(wbase + k * 132);  // LDS.128
            aif0 = fma2(wv.x, h0, aif0);
            ago0 = fma2(wv.y, h0, ago0);
            aif1 = fma2(wv.x, h1, aif1);
            ago1 = fma2(wv.y, h1, ago1);
        }
        float2 vif = unpack2(aif0), vgo = unpack2(ago0);
        float ai = vif.x + ga00, af = vif.y + ga01;
        float ag = vgo.x + ga02, ao = vgo.y + ga03;
        cc.x = sigf(af) * cc.x + sigf(ai) * tanhf(ag);
        float hx = sigf(ao) * tanhf(cc.x);
        vif = unpack2(aif1); vgo = unpack2(ago1);
        ai = vif.x + ga10; af = vif.y + ga11;
        ag = vgo.x + ga12; ao = vgo.y + ga13;
        cc.y = sigf(af) * cc.y + sigf(ai) * tanhf(ag);
        float hy = sigf(ao) * tanhf(cc.y);

        if (s < Sn - 1) {
            // broadcast (hx,hy) into every cluster CTA's next-phase hsm
            ull hp2 = pack2(hx, hy);
            unsigned dst = hbase + (unsigned)((((1 - p) * 256 + (u0 + u)) * 9 + w) * 8);
#pragma unroll
            for (int r = 0; r < 8; r++) {
                asm volatile(
                    "{\n\t.reg .b32 ra;\n\t"
                    "mapa.shared::cluster.u32 ra, %0, %1;\n\t"
                    "st.shared::cluster.u64 [ra], %2;\n\t}"
                    :: "r"(dst), "r"(r), "l"(hp2) : "memory");
            }
            asm volatile("barrier.cluster.arrive.aligned;" ::: "memory");
            asm volatile("barrier.cluster.wait.aligned;" ::: "memory");
        } else {
            float* hb = g_hbuf + (size_t)dir * Bn * Hn;
            hb[(b0 + 2 * w) * Hn + u0 + u] = hx;
            hb[(b0 + 2 * w + 1) * Hn + u0 + u] = hy;
        }
    }
}
#define LSTM3_SMEM (256 * 132 * 4 + 2 * 256 * 9 * 8)   // 135168 + 36864 = 172032

// ---------------- pack final fh|bh into decoder h0 --------------------------
__global__ void pack_h0() {
    int i = blockIdx.x * blockDim.x + threadIdx.x;
    if (i >= Bn * H2) return;
    int b = i >> 9, j = i & 511;
    g_hdec[0][i] = g_hbuf[(size_t)(j >> 8) * Bn * Hn + b * Hn + (j & 255)];
}

// ---------------- generic transpose -----------------------------------------
__global__ void transpose_kernel(const float* __restrict__ in,
                                 float* __restrict__ out, int J, int K) {
    int i = blockIdx.x * blockDim.x + threadIdx.x;
    if (i >= J * K) return;
    int j = i / K, k = i - j * K;
    out[k * J + j] = in[i];
}

// ---------------- decoder input gates ---------------------------------------
__global__ void gxd_kernel(const int* __restrict__ classes,
                           const float* __restrict__ ecW,
                           const float* __restrict__ dWih,
                           const float* __restrict__ dbih) {
    __shared__ float ce[En];
    int c = blockIdx.x;
    int cidx = classes[c];
    for (int e = threadIdx.x; e < En; e += blockDim.x)
        ce[e] = tanhf(ecW[(size_t)cidx * En + e]);
    __syncthreads();
    for (int j = threadIdx.x; j < G3; j += blockDim.x) {
        float acc = dbih[j];
        const float* w = dWih + (size_t)j * En;
        for (int e = 0; e < En; e++) acc += ce[e] * w[e];
        g_gxd[c * G3 + j] = acc;
    }
}

// ---------------- GRU decoder step ------------------------------------------
__global__ void dec_step1(int c, int srcp, const float* __restrict__ dbhh) {
    __shared__ float hsm[16 * H2];
    const float* src = g_hdec[srcp];
    float* dst = g_hdec[1 - srcp];
    int b0 = blockIdx.y * 16;
    int u0 = blockIdx.x * 32;
    int t = threadIdx.x;
    for (int i = t; i < 16 * H2; i += 256)
        hsm[i] = src[(b0 + (i >> 9)) * H2 + (i & 511)];
    __syncthreads();

    int u = u0 + (t & 31);
    int bp = t >> 5;
    const float* h0p = hsm + (bp * 2) * H2;
    const float* h1p = hsm + (bp * 2 + 1) * H2;
    float r0 = 0, z0 = 0, n0 = 0, r1 = 0, z1 = 0, n1 = 0;
    const float* w = g_dT + u;
#pragma unroll 4
    for (int k = 0; k < H2; k++) {
        float wr = w[(size_t)k * G3];
        float wz = w[(size_t)k * G3 + 512];
        float wn = w[(size_t)k * G3 + 1024];
        float x0 = h0p[k], x1 = h1p[k];
        r0 += x0 * wr; z0 += x0 * wz; n0 += x0 * wn;
        r1 += x1 * wr; z1 += x1 * wz; n1 += x1 * wn;
    }
    float br = dbhh[u], bz = dbhh[512 + u], bn = dbhh[1024 + u];
    float gr = g_gxd[c * G3 + u];
    float gz = g_gxd[c * G3 + 512 + u];
    float gn = g_gxd[c * G3 + 1024 + u];

    float R0 = sigf(gr + r0 + br);
    float Z0 = sigf(gz + z0 + bz);
    float N0 = tanhf(gn + R0 * (n0 + bn));
    dst[(b0 + bp * 2) * H2 + u] = tanhf((1.f - Z0) * N0 + Z0 * h0p[u]);

    float R1 = sigf(gr + r1 + br);
    float Z1 = sigf(gz + z1 + bz);
    float N1 = tanhf(gn + R1 * (n1 + bn));
    dst[(b0 + bp * 2 + 1) * H2 + u] = tanhf((1.f - Z1) * N1 + Z1 * h1p[u]);
}

// ---------------- proj + cls + log_softmax ----------------------------------
__global__ void dec_step2(int c, int hp, const float* __restrict__ projb,
                          const float* __restrict__ clsW,
                          const float* __restrict__ clsb,
                          float* __restrict__ out) {
    __shared__ float hsm[H2];
    __shared__ float r0s[256], r1s[256];
    int b = blockIdx.x;
    const float* h = g_hdec[hp] + (size_t)b * H2;
    int t = threadIdx.x;
    hsm[t] = h[t];
    hsm[t + 256] = h[t + 256];
    __syncthreads();
    float p = projb[t];
    const float* w = g_pT + t;
#pragma unroll 4
    for (int k = 0; k < H2; k++) p += hsm[k] * w[(size_t)k * Pn];
    r0s[t] = p * clsW[t];
    r1s[t] = p * clsW[256 + t];
    __syncthreads();
    for (int off = 128; off > 0; off >>= 1) {
        if (t < off) {
            r0s[t] += r0s[t + off];
            r1s[t] += r1s[t + off];
        }
        __syncthreads();
    }
    if (t == 0) {
        float l0 = r0s[0] + clsb[0], l1 = r1s[0] + clsb[1];
        float m = fmaxf(l0, l1);
        float lse = m + logf(expf(l0 - m) + expf(l1 - m));
        out[(c * Bn + b) * 2 + 0] = l0 - lse;
        out[(c * Bn + b) * 2 + 1] = l1 - lse;
    }
}

// ---------------- launch ----------------------------------------------------
extern "C" void kernel_launch(void* const* d_in, const int* in_sizes, int n_in,
                              void* d_out, int out_size) {
    const int*   seq     = (const int*)d_in[0];
    const int*   classes = (const int*)d_in[1];
    const float* embW    = (const float*)d_in[2];
    const float* ecW     = (const float*)d_in[3];
    const float* fWih    = (const float*)d_in[4];
    const float* fWhh    = (const float*)d_in[5];
    const float* fbih    = (const float*)d_in[6];
    const float* fbhh    = (const float*)d_in[7];
    const float* bWih    = (const float*)d_in[8];
    const float* bWhh    = (const float*)d_in[9];
    const float* bbih    = (const float*)d_in[10];
    const float* bbhh    = (const float*)d_in[11];
    const float* dWih    = (const float*)d_in[12];
    const float* dWhh    = (const float*)d_in[13];
    const float* dbih    = (const float*)d_in[14];
    const float* dbhh    = (const float*)d_in[15];
    const float* projW   = (const float*)d_in[16];
    const float* projb   = (const float*)d_in[17];
    const float* clsW    = (const float*)d_in[18];
    const float* clsb    = (const float*)d_in[19];
    float* out = (float*)d_out;

    cudaFuncSetAttribute(lstm3, cudaFuncAttributeMaxDynamicSharedMemorySize,
                         LSTM3_SMEM);
    cudaFuncSetAttribute(sgemm3, cudaFuncAttributeMaxDynamicSharedMemorySize,
                         SGEMM3_SMEM);

    float *emb_p, *gx_p, *Wc_p, *bc_p, *dT_p, *pT_p;
    cudaGetSymbolAddress((void**)&emb_p, g_emb);
    cudaGetSymbolAddress((void**)&gx_p, g_gx);
    cudaGetSymbolAddress((void**)&Wc_p, g_Wc);
    cudaGetSymbolAddress((void**)&bc_p, g_bc);
    cudaGetSymbolAddress((void**)&dT_p, g_dT);
    cudaGetSymbolAddress((void**)&pT_p, g_pT);

    embed_kernel<<<Sn * Bn, 128>>>(seq, embW);
    prep_w<<<(Nc * KP + 255) / 256, 256>>>(fWih, bWih, fbih, fbhh, bbih, bbhh);

    dim3 ggrid(Nc / 128, (Sn * Bn) / 128);
    sgemm3<<<ggrid, 256, SGEMM3_SMEM>>>(emb_p, Wc_p, bc_p, gx_p);

    transpose_kernel<<<(G3 * H2 + 255) / 256, 256>>>(dWhh, dT_p, G3, H2);
    transpose_kernel<<<(Pn * H2 + 255) / 256, 256>>>(projW, pT_p, Pn, H2);
    gxd_kernel<<<Cn, 256>>>(classes, ecW, dWih, dbih);

    lstm3<<<128, 256, LSTM3_SMEM>>>(fWhh, bWhh);
    pack_h0<<<(Bn * H2 + 255) / 256, 256>>>();

    for (int c = 0; c < Cn; c++) {
        int sp = c & 1;
        dim3 dgrid(16, 8);
        dec_step1<<<dgrid, 256>>>(c, sp, dbhh);
        dec_step2<<<Bn, 256>>>(c, 1 - sp, projb, clsW, clsb, out);
    }
}

// round 10
// speedup vs baseline: 1.8192x; 1.8192x over previous
#include <cuda_runtime.h>
#include <math.h>

#define Sn 512
#define Bn 128
#define En 300
#define KP 304          // padded K for GEMM
#define Hn 256
#define Nc 2048         // combined gate width (fwd 1024 | bwd 1024)
#define Cn 6
#define Pn 256
#define H2 512
#define G3 1536

typedef unsigned long long ull;

// ---------------- f32x2 helpers ---------------------------------------------
__device__ __forceinline__ ull fma2(ull a, ull b, ull c) {
    ull d; asm("fma.rn.f32x2 %0, %1, %2, %3;" : "=l"(d) : "l"(a), "l"(b), "l"(c));
    return d;
}
__device__ __forceinline__ ull add2(ull a, ull b) {
    ull d; asm("add.rn.f32x2 %0, %1, %2;" : "=l"(d) : "l"(a), "l"(b));
    return d;
}
__device__ __forceinline__ ull pack2(float x, float y) {
    ull d; asm("mov.b64 %0, {%1, %2};" : "=l"(d) : "f"(x), "f"(y));
    return d;
}
__device__ __forceinline__ float2 unpack2(ull p) {
    float2 r; asm("mov.b64 {%0, %1}, %2;" : "=f"(r.x), "=f"(r.y) : "l"(p));
    return r;
}
__device__ __forceinline__ float sigf(float x) { return 1.f / (1.f + __expf(-x)); }

// ---------------- scratch (static; no cudaMalloc) ---------------------------
__device__ float g_emb[Sn * Bn * KP];          // [S*B][304] zero-padded
__device__ float g_gx[(size_t)Sn * Bn * Nc];   // [S*B][2048] fwd|bwd gates
__device__ float g_Wc[Nc * KP];                // combined padded Wih
__device__ float g_bc[Nc];                     // combined bih+bhh
__device__ float g_hbuf[2 * 2 * Bn * Hn];      // [phase][dir][b][h]
__device__ float g_hdec[2][Bn * H2];
__device__ float g_gxd[Cn * G3];
__device__ float g_dT[H2 * G3];
__device__ float g_pT[H2 * Pn];
__device__ unsigned g_bar2[16];                // [dir][bgroup] barrier counters

// ---------------- reset -----------------------------------------------------
__global__ void reset_kernel() {
    int i = blockIdx.x * blockDim.x + threadIdx.x;
    if (i < 16) g_bar2[i] = 0u;
    for (int j = i; j < 2 * 2 * Bn * Hn; j += gridDim.x * blockDim.x)
        g_hbuf[j] = 0.f;
}

// ---------------- embedding: g_emb[s*128+b][0:300] = tanh(embed_W[tok]) -----
__global__ void embed_kernel(const int* __restrict__ seq,
                             const float* __restrict__ embW) {
    int m = blockIdx.x;              // m = s*128 + b
    int s = m >> 7, b = m & 127;
    int tok = seq[b * Sn + s];
    const float* src = embW + (size_t)tok * En;
    float* dst = g_emb + (size_t)m * KP;
    for (int e = threadIdx.x; e < En; e += blockDim.x)
        dst[e] = tanhf(src[e]);
    for (int e = En + threadIdx.x; e < KP; e += blockDim.x)
        dst[e] = 0.f;
}

// ---------------- build combined padded weights + bias ----------------------
__global__ void prep_w(const float* __restrict__ fWih, const float* __restrict__ bWih,
                       const float* __restrict__ fbih, const float* __restrict__ fbhh,
                       const float* __restrict__ bbih, const float* __restrict__ bbhh) {
    int i = blockIdx.x * blockDim.x + threadIdx.x;
    if (i < Nc * KP) {
        int n = i / KP, e = i - n * KP;
        float v = 0.f;
        if (e < En) v = (n < 1024) ? fWih[n * En + e] : bWih[(n - 1024) * En + e];
        g_Wc[i] = v;
    }
    if (i < Nc)
        g_bc[i] = (i < 1024) ? (fbih[i] + fbhh[i]) : (bbih[i - 1024] + bbhh[i - 1024]);
}

// ---------------- f32x2 SGEMM v3: C[M,2048] = A[M,304]*W[2048,304]^T + bias --
// N-pairs packed in f32x2 lanes (natural W loads, no inner-loop packs);
// A pre-duplicated (a,a) in smem at fill time (broadcast loads).
// BM=BN=128, BK=16, 256 threads, 8m x 8n per thread, double-buffered.
#define ADS 130   // A-dup row stride (ull)
#define WSS 132   // W row stride (float)
__global__ void __launch_bounds__(256, 2)
sgemm3(const float* __restrict__ A, const float* __restrict__ W,
       const float* __restrict__ bias, float* __restrict__ C) {
    extern __shared__ ull dynsm[];
    ull* Ad = dynsm;                          // [2][16][ADS] dup-packed
    float* Wsf = (float*)(dynsm + 2 * 16 * ADS);  // [2][16][WSS]
    int bm = blockIdx.y * 128, bn = blockIdx.x * 128;
    int t = threadIdx.x;
    int tx = t & 15, ty = t >> 4;
    int row = t >> 1;                 // 0..127
    int kc = (t & 1) * 8;             // 0 or 8
    const float* Ap = A + (size_t)(bm + row) * KP + kc;
    const float* Wp = W + (size_t)(bn + row) * KP + kc;

    ull acc[8][4];
#pragma unroll
    for (int i = 0; i < 8; i++)
#pragma unroll
        for (int j = 0; j < 4; j++) acc[i][j] = 0ull;

    float4 a0 = *(const float4*)(Ap);
    float4 a1 = *(const float4*)(Ap + 4);
    float4 w0 = *(const float4*)(Wp);
    float4 w1 = *(const float4*)(Wp + 4);
    {
        ull* ad = Ad; float* ws = Wsf;
        ad[(kc + 0) * ADS + row] = pack2(a0.x, a0.x);
        ad[(kc + 1) * ADS + row] = pack2(a0.y, a0.y);
        ad[(kc + 2) * ADS + row] = pack2(a0.z, a0.z);
        ad[(kc + 3) * ADS + row] = pack2(a0.w, a0.w);
        ad[(kc + 4) * ADS + row] = pack2(a1.x, a1.x);
        ad[(kc + 5) * ADS + row] = pack2(a1.y, a1.y);
        ad[(kc + 6) * ADS + row] = pack2(a1.z, a1.z);
        ad[(kc + 7) * ADS + row] = pack2(a1.w, a1.w);
        ws[(kc + 0) * WSS + row] = w0.x; ws[(kc + 1) * WSS + row] = w0.y;
        ws[(kc + 2) * WSS + row] = w0.z; ws[(kc + 3) * WSS + row] = w0.w;
        ws[(kc + 4) * WSS + row] = w1.x; ws[(kc + 5) * WSS + row] = w1.y;
        ws[(kc + 6) * WSS + row] = w1.z; ws[(kc + 7) * WSS + row] = w1.w;
    }
    __syncthreads();

#pragma unroll 1
    for (int it = 0; it < 19; it++) {
        int buf = it & 1;
        if (it < 18) {
            int k0 = (it + 1) * 16;
            a0 = *(const float4*)(Ap + k0);
            a1 = *(const float4*)(Ap + k0 + 4);
            w0 = *(const float4*)(Wp + k0);
            w1 = *(const float4*)(Wp + k0 + 4);
        }
        const ull* ad = Ad + buf * 16 * ADS;
        const float* ws = Wsf + buf * 16 * WSS;
#pragma unroll 4
        for (int kk = 0; kk < 16; kk++) {
            const ull* ap = ad + kk * ADS + ty * 8;
            ulonglong2 A01 = *(const ulonglong2*)(ap);
            ulonglong2 A23 = *(const ulonglong2*)(ap + 2);
            ulonglong2 A45 = *(const ulonglong2*)(ap + 4);
            ulonglong2 A67 = *(const ulonglong2*)(ap + 6);
            ull am[8] = {A01.x, A01.y, A23.x, A23.y, A45.x, A45.y, A67.x, A67.y};
            const ulonglong2* wp2 = (const ulonglong2*)(ws + kk * WSS + tx * 8);
            ulonglong2 W03 = wp2[0], W47 = wp2[1];
            ull wn[4] = {W03.x, W03.y, W47.x, W47.y};
#pragma unroll
            for (int mi = 0; mi < 8; mi++)
#pragma unroll
                for (int np = 0; np < 4; np++)
                    acc[mi][np] = fma2(am[mi], wn[np], acc[mi][np]);
        }
        if (it < 18) {
            ull* ad2 = Ad + (1 - buf) * 16 * ADS;
            float* ws2 = Wsf + (1 - buf) * 16 * WSS;
            ad2[(kc + 0) * ADS + row] = pack2(a0.x, a0.x);
            ad2[(kc + 1) * ADS + row] = pack2(a0.y, a0.y);
            ad2[(kc + 2) * ADS + row] = pack2(a0.z, a0.z);
            ad2[(kc + 3) * ADS + row] = pack2(a0.w, a0.w);
            ad2[(kc + 4) * ADS + row] = pack2(a1.x, a1.x);
            ad2[(kc + 5) * ADS + row] = pack2(a1.y, a1.y);
            ad2[(kc + 6) * ADS + row] = pack2(a1.z, a1.z);
            ad2[(kc + 7) * ADS + row] = pack2(a1.w, a1.w);
            ws2[(kc + 0) * WSS + row] = w0.x; ws2[(kc + 1) * WSS + row] = w0.y;
            ws2[(kc + 2) * WSS + row] = w0.z; ws2[(kc + 3) * WSS + row] = w0.w;
            ws2[(kc + 4) * WSS + row] = w1.x; ws2[(kc + 5) * WSS + row] = w1.y;
            ws2[(kc + 6) * WSS + row] = w1.z; ws2[(kc + 7) * WSS + row] = w1.w;
            __syncthreads();
        }
    }

    float4 bb0 = *(const float4*)(bias + bn + tx * 8);
    float4 bb1 = *(const float4*)(bias + bn + tx * 8 + 4);
#pragma unroll
    for (int mi = 0; mi < 8; mi++) {
        float2 p0 = unpack2(acc[mi][0]);
        float2 p1 = unpack2(acc[mi][1]);
        float2 p2 = unpack2(acc[mi][2]);
        float2 p3 = unpack2(acc[mi][3]);
        size_t r = (size_t)(bm + ty * 8 + mi);
        float4 o;
        o.x = p0.x + bb0.x; o.y = p0.y + bb0.y; o.z = p1.x + bb0.z; o.w = p1.y + bb0.w;
        *(float4*)(C + r * Nc + bn + tx * 8) = o;
        o.x = p2.x + bb1.x; o.y = p2.y + bb1.y; o.z = p3.x + bb1.z; o.w = p3.y + bb1.w;
        *(float4*)(C + r * Nc + bn + tx * 8 + 4) = o;
    }
}
#define SGEMM3_SMEM (2 * 16 * ADS * 8 + 2 * 16 * WSS * 4)   // 50176 B

// ---------------- persistent bidirectional LSTM recurrence (R8-proven) ------
// 128 CTAs: dir = blk>>6. CTA tile: 16 batches (bg) x 32 units (u0).
// Warps partition K (each weight read by exactly ONE warp); f32x2 packs batch
// pairs; cross-warp smem reduction; 8-CTA group barriers.
__global__ void __launch_bounds__(256, 1)
lstm2(const float* __restrict__ fWhh, const float* __restrict__ bWhh) {
    extern __shared__ float sm[];
    float* Wsm = sm;                       // [256 k][129 pad] (g*32+u in 0..127)
    ull* red = (ull*)(sm + 256 * 129);     // [8 w][4 g][8 bp][32 u]
    ull* hsm = red + 8192;                 // [256 k][9 pad] batch pairs

    int dir = blockIdx.x >> 6;
    int L = blockIdx.x & 63;
    int bg = L >> 3, u0 = (L & 7) * 32;
    int b0 = bg * 16;
    const float* Whh = dir ? bWhh : fWhh;
    const float* gx = g_gx + dir * 1024;
    int t = threadIdx.x, w = t >> 5, u = t & 31;

    // load Whh slice: Wsm[k*129 + g*32+uu] = Whh[(g*256+u0+uu)*256 + k]
    for (int i = t; i < 32768; i += 256) {
        int k = i & 255, r = i >> 8;
        int g = r >> 5, uu = r & 31;
        Wsm[k * 129 + r] = Whh[(size_t)(g * Hn + u0 + uu) * Hn + k];
    }
    float2 cc = make_float2(0.f, 0.f);
    volatile unsigned* cnt = &g_bar2[dir * 8 + bg];
    __syncthreads();

    for (int s = 0; s < Sn; s++) {
        int p = s & 1;
        // 1. transpose h_prev -> pair-packed hsm[k][bp]
        const float* hprev = g_hbuf + (size_t)(p * 2 + dir) * Bn * Hn;
#pragma unroll
        for (int j = 0; j < 16; j++) {
            float v = hprev[(b0 + j) * Hn + t];
            ((float*)(hsm + (t * 9 + (j >> 1))))[j & 1] = v;
        }
        __syncthreads();

        // prefetch gx for this thread's outputs (owner: bp=w, u)
        int xs = dir ? ((Sn - s) & (Sn - 1)) : s;
        const float* gp = gx + ((size_t)(xs * Bn + b0 + 2 * w)) * Nc + u0 + u;
        float ga0[4], ga1[4];
#pragma unroll
        for (int g = 0; g < 4; g++) {
            ga0[g] = gp[g * Hn];
            ga1[g] = gp[Nc + g * Hn];
        }

        // 2. partial gate dots over this warp's k slice
        ull acc[4][8];
#pragma unroll
        for (int g = 0; g < 4; g++)
#pragma unroll
            for (int bp = 0; bp < 8; bp++) acc[g][bp] = 0ull;
#pragma unroll 4
        for (int kk = 0; kk < 32; kk++) {
            int k = w * 32 + kk;
            const ull* hp = hsm + k * 9;
            ull hv[8] = {hp[0], hp[1], hp[2], hp[3], hp[4], hp[5], hp[6], hp[7]};
            const float* wr = Wsm + k * 129 + u;
            ull W0 = pack2(wr[0], wr[0]);
            ull W1 = pack2(wr[32], wr[32]);
            ull W2 = pack2(wr[64], wr[64]);
            ull W3 = pack2(wr[96], wr[96]);
#pragma unroll
            for (int bp = 0; bp < 8; bp++) {
                acc[0][bp] = fma2(W0, hv[bp], acc[0][bp]);
                acc[1][bp] = fma2(W1, hv[bp], acc[1][bp]);
                acc[2][bp] = fma2(W2, hv[bp], acc[2][bp]);
                acc[3][bp] = fma2(W3, hv[bp], acc[3][bp]);
            }
        }
        // 3. stash partials
#pragma unroll
        for (int g = 0; g < 4; g++)
#pragma unroll
            for (int bp = 0; bp < 8; bp++)
                red[((w * 4 + g) * 8 + bp) * 32 + u] = acc[g][bp];
        __syncthreads();

        // 4. reduce across warps; thread owns (bp=w, u)
        ull s0 = pack2(ga0[0], ga1[0]);
        ull s1 = pack2(ga0[1], ga1[1]);
        ull s2 = pack2(ga0[2], ga1[2]);
        ull s3 = pack2(ga0[3], ga1[3]);
#pragma unroll
        for (int ww = 0; ww < 8; ww++) {
            const ull* rp = red + ((ww * 4) * 8 + w) * 32 + u;
            s0 = add2(s0, rp[0]);
            s1 = add2(s1, rp[8 * 32]);
            s2 = add2(s2, rp[16 * 32]);
            s3 = add2(s3, rp[24 * 32]);
        }
        float2 iv = unpack2(s0), fv = unpack2(s1), gv = unpack2(s2), ov = unpack2(s3);
        cc.x = sigf(fv.x) * cc.x + sigf(iv.x) * tanhf(gv.x);
        cc.y = sigf(fv.y) * cc.y + sigf(iv.y) * tanhf(gv.y);
        float hx = sigf(ov.x) * tanhf(cc.x);
        float hy = sigf(ov.y) * tanhf(cc.y);

        // 5. publish h_new
        float* hnew = g_hbuf + (size_t)((1 - p) * 2 + dir) * Bn * Hn;
        hnew[(b0 + 2 * w) * Hn + u0 + u] = hx;
        hnew[(b0 + 2 * w + 1) * Hn + u0 + u] = hy;

        __syncthreads();
        // 6. 8-CTA group barrier (same dir, same bg)
        if (s < Sn - 1) {
            if (t == 0) {
                __threadfence();
                atomicAdd(&g_bar2[dir * 8 + bg], 1u);
                unsigned tgt = (unsigned)(s + 1) * 8u;
                while (*cnt < tgt) { __nanosleep(40); }
                __threadfence();
            }
            __syncthreads();
        }
    }
}
#define LSTM2_SMEM (256 * 129 * 4 + 8192 * 8 + 2304 * 8)   // 216064 B

// ---------------- pack final fh|bh into decoder h0 --------------------------
__global__ void pack_h0() {
    int i = blockIdx.x * blockDim.x + threadIdx.x;
    if (i >= Bn * H2) return;
    int b = i >> 9, j = i & 511;
    // final h is in phase 0: [0][dir][b][k]
    g_hdec[0][i] = g_hbuf[(size_t)(j >> 8) * Bn * Hn + b * Hn + (j & 255)];
}

// ---------------- generic transpose -----------------------------------------
__global__ void transpose_kernel(const float* __restrict__ in,
                                 float* __restrict__ out, int J, int K) {
    int i = blockIdx.x * blockDim.x + threadIdx.x;
    if (i >= J * K) return;
    int j = i / K, k = i - j * K;
    out[k * J + j] = in[i];
}

// ---------------- decoder input gates ---------------------------------------
__global__ void gxd_kernel(const int* __restrict__ classes,
                           const float* __restrict__ ecW,
                           const float* __restrict__ dWih,
                           const float* __restrict__ dbih) {
    __shared__ float ce[En];
    int c = blockIdx.x;
    int cidx = classes[c];
    for (int e = threadIdx.x; e < En; e += blockDim.x)
        ce[e] = tanhf(ecW[(size_t)cidx * En + e]);
    __syncthreads();
    for (int j = threadIdx.x; j < G3; j += blockDim.x) {
        float acc = dbih[j];
        const float* w = dWih + (size_t)j * En;
        for (int e = 0; e < En; e++) acc += ce[e] * w[e];
        g_gxd[c * G3 + j] = acc;
    }
}

// ---------------- GRU decoder step ------------------------------------------
__global__ void dec_step1(int c, int srcp, const float* __restrict__ dbhh) {
    __shared__ float hsm[16 * H2];
    const float* src = g_hdec[srcp];
    float* dst = g_hdec[1 - srcp];
    int b0 = blockIdx.y * 16;
    int u0 = blockIdx.x * 32;
    int t = threadIdx.x;
    for (int i = t; i < 16 * H2; i += 256)
        hsm[i] = src[(b0 + (i >> 9)) * H2 + (i & 511)];
    __syncthreads();

    int u = u0 + (t & 31);
    int bp = t >> 5;
    const float* h0p = hsm + (bp * 2) * H2;
    const float* h1p = hsm + (bp * 2 + 1) * H2;
    float r0 = 0, z0 = 0, n0 = 0, r1 = 0, z1 = 0, n1 = 0;
    const float* w = g_dT + u;
#pragma unroll 4
    for (int k = 0; k < H2; k++) {
        float wr = w[(size_t)k * G3];
        float wz = w[(size_t)k * G3 + 512];
        float wn = w[(size_t)k * G3 + 1024];
        float x0 = h0p[k], x1 = h1p[k];
        r0 += x0 * wr; z0 += x0 * wz; n0 += x0 * wn;
        r1 += x1 * wr; z1 += x1 * wz; n1 += x1 * wn;
    }
    float br = dbhh[u], bz = dbhh[512 + u], bn = dbhh[1024 + u];
    float gr = g_gxd[c * G3 + u];
    float gz = g_gxd[c * G3 + 512 + u];
    float gn = g_gxd[c * G3 + 1024 + u];

    float R0 = sigf(gr + r0 + br);
    float Z0 = sigf(gz + z0 + bz);
    float N0 = tanhf(gn + R0 * (n0 + bn));
    dst[(b0 + bp * 2) * H2 + u] = tanhf((1.f - Z0) * N0 + Z0 * h0p[u]);

    float R1 = sigf(gr + r1 + br);
    float Z1 = sigf(gz + z1 + bz);
    float N1 = tanhf(gn + R1 * (n1 + bn));
    dst[(b0 + bp * 2 + 1) * H2 + u] = tanhf((1.f - Z1) * N1 + Z1 * h1p[u]);
}

// ---------------- proj + cls + log_softmax ----------------------------------
__global__ void dec_step2(int c, int hp, const float* __restrict__ projb,
                          const float* __restrict__ clsW,
                          const float* __restrict__ clsb,
                          float* __restrict__ out) {
    __shared__ float hsm[H2];
    __shared__ float r0s[256], r1s[256];
    int b = blockIdx.x;
    const float* h = g_hdec[hp] + (size_t)b * H2;
    int t = threadIdx.x;
    hsm[t] = h[t];
    hsm[t + 256] = h[t + 256];
    __syncthreads();
    float p = projb[t];
    const float* w = g_pT + t;
#pragma unroll 4
    for (int k = 0; k < H2; k++) p += hsm[k] * w[(size_t)k * Pn];
    r0s[t] = p * clsW[t];
    r1s[t] = p * clsW[256 + t];
    __syncthreads();
    for (int off = 128; off > 0; off >>= 1) {
        if (t < off) {
            r0s[t] += r0s[t + off];
            r1s[t] += r1s[t + off];
        }
        __syncthreads();
    }
    if (t == 0) {
        float l0 = r0s[0] + clsb[0], l1 = r1s[0] + clsb[1];
        float m = fmaxf(l0, l1);
        float lse = m + logf(expf(l0 - m) + expf(l1 - m));
        out[(c * Bn + b) * 2 + 0] = l0 - lse;
        out[(c * Bn + b) * 2 + 1] = l1 - lse;
    }
}

// ---------------- launch ----------------------------------------------------
extern "C" void kernel_launch(void* const* d_in, const int* in_sizes, int n_in,
                              void* d_out, int out_size) {
    const int*   seq     = (const int*)d_in[0];
    const int*   classes = (const int*)d_in[1];
    const float* embW    = (const float*)d_in[2];
    const float* ecW     = (const float*)d_in[3];
    const float* fWih    = (const float*)d_in[4];
    const float* fWhh    = (const float*)d_in[5];
    const float* fbih    = (const float*)d_in[6];
    const float* fbhh    = (const float*)d_in[7];
    const float* bWih    = (const float*)d_in[8];
    const float* bWhh    = (const float*)d_in[9];
    const float* bbih    = (const float*)d_in[10];
    const float* bbhh    = (const float*)d_in[11];
    const float* dWih    = (const float*)d_in[12];
    const float* dWhh    = (const float*)d_in[13];
    const float* dbih    = (const float*)d_in[14];
    const float* dbhh    = (const float*)d_in[15];
    const float* projW   = (const float*)d_in[16];
    const float* projb   = (const float*)d_in[17];
    const float* clsW    = (const float*)d_in[18];
    const float* clsb    = (const float*)d_in[19];
    float* out = (float*)d_out;

    cudaFuncSetAttribute(lstm2, cudaFuncAttributeMaxDynamicSharedMemorySize,
                         LSTM2_SMEM);
    cudaFuncSetAttribute(sgemm3, cudaFuncAttributeMaxDynamicSharedMemorySize,
                         SGEMM3_SMEM);

    float *emb_p, *gx_p, *Wc_p, *bc_p, *dT_p, *pT_p;
    cudaGetSymbolAddress((void**)&emb_p, g_emb);
    cudaGetSymbolAddress((void**)&gx_p, g_gx);
    cudaGetSymbolAddress((void**)&Wc_p, g_Wc);
    cudaGetSymbolAddress((void**)&bc_p, g_bc);
    cudaGetSymbolAddress((void**)&dT_p, g_dT);
    cudaGetSymbolAddress((void**)&pT_p, g_pT);

    reset_kernel<<<64, 256>>>();
    embed_kernel<<<Sn * Bn, 128>>>(seq, embW);
    prep_w<<<(Nc * KP + 255) / 256, 256>>>(fWih, bWih, fbih, fbhh, bbih, bbhh);

    dim3 ggrid(Nc / 128, (Sn * Bn) / 128);
    sgemm3<<<ggrid, 256, SGEMM3_SMEM>>>(emb_p, Wc_p, bc_p, gx_p);

    transpose_kernel<<<(G3 * H2 + 255) / 256, 256>>>(dWhh, dT_p, G3, H2);
    transpose_kernel<<<(Pn * H2 + 255) / 256, 256>>>(projW, pT_p, Pn, H2);
    gxd_kernel<<<Cn, 256>>>(classes, ecW, dWih, dbih);

    lstm2<<<128, 256, LSTM2_SMEM>>>(fWhh, bWhh);
    pack_h0<<<(Bn * H2 + 255) / 256, 256>>>();

    for (int c = 0; c < Cn; c++) {
        int sp = c & 1;
        dim3 dgrid(16, 8);
        dec_step1<<<dgrid, 256>>>(c, sp, dbhh);
        dec_step2<<<Bn, 256>>>(c, 1 - sp, projb, clsW, clsb, out);
    }
}

// round 12
// speedup vs baseline: 1.9045x; 1.0469x over previous
#include <cuda_runtime.h>
#include <math.h>

#define Sn 512
#define Bn 128
#define En 300
#define KP 304          // padded K for GEMM
#define Hn 256
#define Nc 2048         // combined gate width (fwd 1024 | bwd 1024)
#define Cn 6
#define Pn 256
#define H2 512
#define G3 1536
#define SAS 132         // padded smem tile stride in GEMM

typedef unsigned long long ull;

// ---------------- f32x2 helpers ---------------------------------------------
__device__ __forceinline__ ull fma2(ull a, ull b, ull c) {
    ull d; asm("fma.rn.f32x2 %0, %1, %2, %3;" : "=l"(d) : "l"(a), "l"(b), "l"(c));
    return d;
}
__device__ __forceinline__ ull add2(ull a, ull b) {
    ull d; asm("add.rn.f32x2 %0, %1, %2;" : "=l"(d) : "l"(a), "l"(b));
    return d;
}
__device__ __forceinline__ ull pack2(float x, float y) {
    ull d; asm("mov.b64 %0, {%1, %2};" : "=l"(d) : "f"(x), "f"(y));
    return d;
}
__device__ __forceinline__ float2 unpack2(ull p) {
    float2 r; asm("mov.b64 {%0, %1}, %2;" : "=f"(r.x), "=f"(r.y) : "l"(p));
    return r;
}
__device__ __forceinline__ float sigf(float x) { return 1.f / (1.f + __expf(-x)); }
// exact identity tanh(x) = 1 - 2/(e^{2x}+1); __expf error ~2ulp, abs err ~1e-7
__device__ __forceinline__ float tanhfast(float x) {
    float e = __expf(2.f * x);
    return 1.f - __fdividef(2.f, e + 1.f);
}

// ---------------- scratch (static; no cudaMalloc) ---------------------------
__device__ float g_emb[Sn * Bn * KP];          // [S*B][304] zero-padded
__device__ float g_gx[(size_t)Sn * Bn * Nc];   // [S*B][2048] fwd|bwd gates
__device__ float g_Wc[Nc * KP];                // combined padded Wih
__device__ float g_bc[Nc];                     // combined bih+bhh
__device__ float g_hbuf[2 * 2 * Bn * Hn];      // [phase][dir][b][h]
__device__ float g_hdec[2][Bn * H2];
__device__ float g_gxd[Cn * G3];
__device__ float g_dT[H2 * G3];
__device__ float g_pT[H2 * Pn];
__device__ unsigned g_bar2[16];                // [dir][bgroup] barrier counters

// ---------------- reset -----------------------------------------------------
__global__ void reset_kernel() {
    int i = blockIdx.x * blockDim.x + threadIdx.x;
    if (i < 16) g_bar2[i] = 0u;
    for (int j = i; j < 2 * 2 * Bn * Hn; j += gridDim.x * blockDim.x)
        g_hbuf[j] = 0.f;
}

// ---------------- embedding: g_emb[s*128+b][0:300] = tanh(embed_W[tok]) -----
__global__ void embed_kernel(const int* __restrict__ seq,
                             const float* __restrict__ embW) {
    int m = blockIdx.x;              // m = s*128 + b
    int s = m >> 7, b = m & 127;
    int tok = seq[b * Sn + s];
    const float* src = embW + (size_t)tok * En;
    float* dst = g_emb + (size_t)m * KP;
    for (int e = threadIdx.x; e < En; e += blockDim.x)
        dst[e] = tanhfast(src[e]);
    for (int e = En + threadIdx.x; e < KP; e += blockDim.x)
        dst[e] = 0.f;
}

// ---------------- build combined padded weights + bias ----------------------
__global__ void prep_w(const float* __restrict__ fWih, const float* __restrict__ bWih,
                       const float* __restrict__ fbih, const float* __restrict__ fbhh,
                       const float* __restrict__ bbih, const float* __restrict__ bbhh) {
    int i = blockIdx.x * blockDim.x + threadIdx.x;
    if (i < Nc * KP) {
        int n = i / KP, e = i - n * KP;
        float v = 0.f;
        if (e < En) v = (n < 1024) ? fWih[n * En + e] : bWih[(n - 1024) * En + e];
        g_Wc[i] = v;
    }
    if (i < Nc)
        g_bc[i] = (i < 1024) ? (fbih[i] + fbhh[i]) : (bbih[i - 1024] + bbhh[i - 1024]);
}

// ---------------- f32x2 SGEMM (R8-proven): C = A * W^T + bias ----------------
// BM=BN=128, BK=16, 256 threads, 8x8 per thread on m-pairs, double-buffered.
__global__ void __launch_bounds__(256, 2)
sgemm2(const float* __restrict__ A, const float* __restrict__ W,
       const float* __restrict__ bias, float* __restrict__ C) {
    __shared__ float As[2][16 * SAS];
    __shared__ float Ws[2][16 * SAS];
    int bm = blockIdx.y * 128, bn = blockIdx.x * 128;
    int t = threadIdx.x;
    int tx = t & 15, ty = t >> 4;
    int row0 = t >> 2, c0 = t & 3;   // j0: rows 0..63
    int row1 = row0 + 64;            // j1: rows 64..127
    const float* Ap0 = A + (size_t)(bm + row0) * KP + c0 * 4;
    const float* Ap1 = A + (size_t)(bm + row1) * KP + c0 * 4;
    const float* Wp0 = W + (size_t)(bn + row0) * KP + c0 * 4;
    const float* Wp1 = W + (size_t)(bn + row1) * KP + c0 * 4;

    ull acc[4][8];
#pragma unroll
    for (int i = 0; i < 4; i++)
#pragma unroll
        for (int j = 0; j < 8; j++) acc[i][j] = 0ull;

    float4 ra0 = *(const float4*)(Ap0);
    float4 ra1 = *(const float4*)(Ap1);
    float4 rw0 = *(const float4*)(Wp0);
    float4 rw1 = *(const float4*)(Wp1);
    {
        float* as = As[0]; float* ws = Ws[0];
        int kb = c0 * 4;
        as[(kb + 0) * SAS + row0] = ra0.x; as[(kb + 1) * SAS + row0] = ra0.y;
        as[(kb + 2) * SAS + row0] = ra0.z; as[(kb + 3) * SAS + row0] = ra0.w;
        as[(kb + 0) * SAS + row1] = ra1.x; as[(kb + 1) * SAS + row1] = ra1.y;
        as[(kb + 2) * SAS + row1] = ra1.z; as[(kb + 3) * SAS + row1] = ra1.w;
        ws[(kb + 0) * SAS + row0] = rw0.x; ws[(kb + 1) * SAS + row0] = rw0.y;
        ws[(kb + 2) * SAS + row0] = rw0.z; ws[(kb + 3) * SAS + row0] = rw0.w;
        ws[(kb + 0) * SAS + row1] = rw1.x; ws[(kb + 1) * SAS + row1] = rw1.y;
        ws[(kb + 2) * SAS + row1] = rw1.z; ws[(kb + 3) * SAS + row1] = rw1.w;
    }
    __syncthreads();

#pragma unroll 1
    for (int it = 0; it < 19; it++) {
        int buf = it & 1;
        if (it < 18) {
            int k0 = (it + 1) * 16;
            ra0 = *(const float4*)(Ap0 + k0);
            ra1 = *(const float4*)(Ap1 + k0);
            rw0 = *(const float4*)(Wp0 + k0);
            rw1 = *(const float4*)(Wp1 + k0);
        }
        const float* as = As[buf];
        const float* ws = Ws[buf];
#pragma unroll 4
        for (int kk = 0; kk < 16; kk++) {
            const ull* ap = (const ull*)(as + kk * SAS + ty * 8);
            ull am[4] = {ap[0], ap[1], ap[2], ap[3]};
            const float4* bp = (const float4*)(ws + kk * SAS + tx * 8);
            float4 b0 = bp[0], b1 = bp[1];
            ull wv[8] = {pack2(b0.x, b0.x), pack2(b0.y, b0.y),
                         pack2(b0.z, b0.z), pack2(b0.w, b0.w),
                         pack2(b1.x, b1.x), pack2(b1.y, b1.y),
                         pack2(b1.z, b1.z), pack2(b1.w, b1.w)};
#pragma unroll
            for (int mp = 0; mp < 4; mp++)
#pragma unroll
                for (int n = 0; n < 8; n++)
                    acc[mp][n] = fma2(am[mp], wv[n], acc[mp][n]);
        }
        if (it < 18) {
            float* as2 = As[1 - buf]; float* ws2 = Ws[1 - buf];
            int kb = c0 * 4;
            as2[(kb + 0) * SAS + row0] = ra0.x; as2[(kb + 1) * SAS + row0] = ra0.y;
            as2[(kb + 2) * SAS + row0] = ra0.z; as2[(kb + 3) * SAS + row0] = ra0.w;
            as2[(kb + 0) * SAS + row1] = ra1.x; as2[(kb + 1) * SAS + row1] = ra1.y;
            as2[(kb + 2) * SAS + row1] = ra1.z; as2[(kb + 3) * SAS + row1] = ra1.w;
            ws2[(kb + 0) * SAS + row0] = rw0.x; ws2[(kb + 1) * SAS + row0] = rw0.y;
            ws2[(kb + 2) * SAS + row0] = rw0.z; ws2[(kb + 3) * SAS + row0] = rw0.w;
            ws2[(kb + 0) * SAS + row1] = rw1.x; ws2[(kb + 1) * SAS + row1] = rw1.y;
            ws2[(kb + 2) * SAS + row1] = rw1.z; ws2[(kb + 3) * SAS + row1] = rw1.w;
            __syncthreads();
        }
    }

    float4 bb0 = *(const float4*)(bias + bn + tx * 8);
    float4 bb1 = *(const float4*)(bias + bn + tx * 8 + 4);
#pragma unroll
    for (int mp = 0; mp < 4; mp++) {
        float2 h[8];
#pragma unroll
        for (int n = 0; n < 8; n++) h[n] = unpack2(acc[mp][n]);
        size_t m0 = (size_t)(bm + ty * 8 + mp * 2);
        float4 o;
        o.x = h[0].x + bb0.x; o.y = h[1].x + bb0.y; o.z = h[2].x + bb0.z; o.w = h[3].x + bb0.w;
        *(float4*)(C + m0 * Nc + bn + tx * 8) = o;
        o.x = h[4].x + bb1.x; o.y = h[5].x + bb1.y; o.z = h[6].x + bb1.z; o.w = h[7].x + bb1.w;
        *(float4*)(C + m0 * Nc + bn + tx * 8 + 4) = o;
        o.x = h[0].y + bb0.x; o.y = h[1].y + bb0.y; o.z = h[2].y + bb0.z; o.w = h[3].y + bb0.w;
        *(float4*)(C + (m0 + 1) * Nc + bn + tx * 8) = o;
        o.x = h[4].y + bb1.x; o.y = h[5].y + bb1.y; o.z = h[6].y + bb1.z; o.w = h[7].y + bb1.w;
        *(float4*)(C + (m0 + 1) * Nc + bn + tx * 8 + 4) = o;
    }
}

// ---------------- persistent bidirectional LSTM recurrence (R8 + fast ops) ---
__global__ void __launch_bounds__(256, 1)
lstm2(const float* __restrict__ fWhh, const float* __restrict__ bWhh) {
    extern __shared__ float sm[];
    float* Wsm = sm;                       // [256 k][129 pad] (g*32+u in 0..127)
    ull* red = (ull*)(sm + 256 * 129);     // [8 w][4 g][8 bp][32 u]
    ull* hsm = red + 8192;                 // [256 k][9 pad] batch pairs

    int dir = blockIdx.x >> 6;
    int L = blockIdx.x & 63;
    int bg = L >> 3, u0 = (L & 7) * 32;
    int b0 = bg * 16;
    const float* Whh = dir ? bWhh : fWhh;
    const float* gx = g_gx + dir * 1024;
    int t = threadIdx.x, w = t >> 5, u = t & 31;

    // load Whh slice: Wsm[k*129 + g*32+uu] = Whh[(g*256+u0+uu)*256 + k]
    for (int i = t; i < 32768; i += 256) {
        int k = i & 255, r = i >> 8;
        int g = r >> 5, uu = r & 31;
        Wsm[k * 129 + r] = Whh[(size_t)(g * Hn + u0 + uu) * Hn + k];
    }
    float2 cc = make_float2(0.f, 0.f);
    unsigned* cnt = &g_bar2[dir * 8 + bg];
    __syncthreads();

    for (int s = 0; s < Sn; s++) {
        int p = s & 1;
        // 1. transpose h_prev -> pair-packed hsm[k][bp]
        const float* hprev = g_hbuf + (size_t)(p * 2 + dir) * Bn * Hn;
#pragma unroll
        for (int j = 0; j < 16; j++) {
            float v = hprev[(b0 + j) * Hn + t];
            ((float*)(hsm + (t * 9 + (j >> 1))))[j & 1] = v;
        }
        __syncthreads();

        // prefetch gx for this thread's outputs (owner: bp=w, u)
        int xs = dir ? ((Sn - s) & (Sn - 1)) : s;
        const float* gp = gx + ((size_t)(xs * Bn + b0 + 2 * w)) * Nc + u0 + u;
        float ga0[4], ga1[4];
#pragma unroll
        for (int g = 0; g < 4; g++) {
            ga0[g] = gp[g * Hn];
            ga1[g] = gp[Nc + g * Hn];
        }

        // 2. partial gate dots over this warp's k slice
        ull acc[4][8];
#pragma unroll
        for (int g = 0; g < 4; g++)
#pragma unroll
            for (int bp = 0; bp < 8; bp++) acc[g][bp] = 0ull;
#pragma unroll 4
        for (int kk = 0; kk < 32; kk++) {
            int k = w * 32 + kk;
            const ull* hp = hsm + k * 9;
            ull hv[8] = {hp[0], hp[1], hp[2], hp[3], hp[4], hp[5], hp[6], hp[7]};
            const float* wr = Wsm + k * 129 + u;
            ull W0 = pack2(wr[0], wr[0]);
            ull W1 = pack2(wr[32], wr[32]);
            ull W2 = pack2(wr[64], wr[64]);
            ull W3 = pack2(wr[96], wr[96]);
#pragma unroll
            for (int bp = 0; bp < 8; bp++) {
                acc[0][bp] = fma2(W0, hv[bp], acc[0][bp]);
                acc[1][bp] = fma2(W1, hv[bp], acc[1][bp]);
                acc[2][bp] = fma2(W2, hv[bp], acc[2][bp]);
                acc[3][bp] = fma2(W3, hv[bp], acc[3][bp]);
            }
        }
        // 3. stash partials
#pragma unroll
        for (int g = 0; g < 4; g++)
#pragma unroll
            for (int bp = 0; bp < 8; bp++)
                red[((w * 4 + g) * 8 + bp) * 32 + u] = acc[g][bp];
        __syncthreads();

        // 4. reduce across warps; thread owns (bp=w, u)
        ull s0 = pack2(ga0[0], ga1[0]);
        ull s1 = pack2(ga0[1], ga1[1]);
        ull s2 = pack2(ga0[2], ga1[2]);
        ull s3 = pack2(ga0[3], ga1[3]);
#pragma unroll
        for (int ww = 0; ww < 8; ww++) {
            const ull* rp = red + ((ww * 4) * 8 + w) * 32 + u;
            s0 = add2(s0, rp[0]);
            s1 = add2(s1, rp[8 * 32]);
            s2 = add2(s2, rp[16 * 32]);
            s3 = add2(s3, rp[24 * 32]);
        }
        float2 iv = unpack2(s0), fv = unpack2(s1), gv = unpack2(s2), ov = unpack2(s3);
        cc.x = sigf(fv.x) * cc.x + sigf(iv.x) * tanhfast(gv.x);
        cc.y = sigf(fv.y) * cc.y + sigf(iv.y) * tanhfast(gv.y);
        float hx = sigf(ov.x) * tanhfast(cc.x);
        float hy = sigf(ov.y) * tanhfast(cc.y);

        // 5. publish h_new
        float* hnew = g_hbuf + (size_t)((1 - p) * 2 + dir) * Bn * Hn;
        hnew[(b0 + 2 * w) * Hn + u0 + u] = hx;
        hnew[(b0 + 2 * w + 1) * Hn + u0 + u] = hy;

        __syncthreads();
        // 6. 8-CTA group barrier (same dir, same bg) — release/acquire
        if (s < Sn - 1) {
            if (t == 0) {
                asm volatile("red.release.gpu.global.add.u32 [%0], %1;"
                             :: "l"(cnt), "r"(1u) : "memory");
                unsigned tgt = (unsigned)(s + 1) * 8u;
                unsigned v;
                do {
                    asm volatile("ld.acquire.gpu.global.u32 %0, [%1];"
                                 : "=r"(v) : "l"(cnt) : "memory");
                } while (v < tgt);
            }
            __syncthreads();
        }
    }
}
#define LSTM2_SMEM (256 * 129 * 4 + 8192 * 8 + 2304 * 8)   // 216064 B

// ---------------- pack final fh|bh into decoder h0 --------------------------
__global__ void pack_h0() {
    int i = blockIdx.x * blockDim.x + threadIdx.x;
    if (i >= Bn * H2) return;
    int b = i >> 9, j = i & 511;
    // final h is in phase 0: [0][dir][b][k]
    g_hdec[0][i] = g_hbuf[(size_t)(j >> 8) * Bn * Hn + b * Hn + (j & 255)];
}

// ---------------- generic transpose -----------------------------------------
__global__ void transpose_kernel(const float* __restrict__ in,
                                 float* __restrict__ out, int J, int K) {
    int i = blockIdx.x * blockDim.x + threadIdx.x;
    if (i >= J * K) return;
    int j = i / K, k = i - j * K;
    out[k * J + j] = in[i];
}

// ---------------- decoder input gates ---------------------------------------
__global__ void gxd_kernel(const int* __restrict__ classes,
                           const float* __restrict__ ecW,
                           const float* __restrict__ dWih,
                           const float* __restrict__ dbih) {
    __shared__ float ce[En];
    int c = blockIdx.x;
    int cidx = classes[c];
    for (int e = threadIdx.x; e < En; e += blockDim.x)
        ce[e] = tanhfast(ecW[(size_t)cidx * En + e]);
    __syncthreads();
    for (int j = threadIdx.x; j < G3; j += blockDim.x) {
        float acc = dbih[j];
        const float* w = dWih + (size_t)j * En;
        for (int e = 0; e < En; e++) acc += ce[e] * w[e];
        g_gxd[c * G3 + j] = acc;
    }
}

// ---------------- GRU decoder step ------------------------------------------
__global__ void dec_step1(int c, int srcp, const float* __restrict__ dbhh) {
    __shared__ float hsm[16 * H2];
    const float* src = g_hdec[srcp];
    float* dst = g_hdec[1 - srcp];
    int b0 = blockIdx.y * 16;
    int u0 = blockIdx.x * 32;
    int t = threadIdx.x;
    for (int i = t; i < 16 * H2; i += 256)
        hsm[i] = src[(b0 + (i >> 9)) * H2 + (i & 511)];
    __syncthreads();

    int u = u0 + (t & 31);
    int bp = t >> 5;
    const float* h0p = hsm + (bp * 2) * H2;
    const float* h1p = hsm + (bp * 2 + 1) * H2;
    float r0 = 0, z0 = 0, n0 = 0, r1 = 0, z1 = 0, n1 = 0;
    const float* w = g_dT + u;
#pragma unroll 4
    for (int k = 0; k < H2; k++) {
        float wr = w[(size_t)k * G3];
        float wz = w[(size_t)k * G3 + 512];
        float wn = w[(size_t)k * G3 + 1024];
        float x0 = h0p[k], x1 = h1p[k];
        r0 += x0 * wr; z0 += x0 * wz; n0 += x0 * wn;
        r1 += x1 * wr; z1 += x1 * wz; n1 += x1 * wn;
    }
    float br = dbhh[u], bz = dbhh[512 + u], bn = dbhh[1024 + u];
    float gr = g_gxd[c * G3 + u];
    float gz = g_gxd[c * G3 + 512 + u];
    float gn = g_gxd[c * G3 + 1024 + u];

    float R0 = sigf(gr + r0 + br);
    float Z0 = sigf(gz + z0 + bz);
    float N0 = tanhfast(gn + R0 * (n0 + bn));
    dst[(b0 + bp * 2) * H2 + u] = tanhfast((1.f - Z0) * N0 + Z0 * h0p[u]);

    float R1 = sigf(gr + r1 + br);
    float Z1 = sigf(gz + z1 + bz);
    float N1 = tanhfast(gn + R1 * (n1 + bn));
    dst[(b0 + bp * 2 + 1) * H2 + u] = tanhfast((1.f - Z1) * N1 + Z1 * h1p[u]);
}

// ---------------- proj + cls + log_softmax ----------------------------------
__global__ void dec_step2(int c, int hp, const float* __restrict__ projb,
                          const float* __restrict__ clsW,
                          const float* __restrict__ clsb,
                          float* __restrict__ out) {
    __shared__ float hsm[H2];
    __shared__ float r0s[256], r1s[256];
    int b = blockIdx.x;
    const float* h = g_hdec[hp] + (size_t)b * H2;
    int t = threadIdx.x;
    hsm[t] = h[t];
    hsm[t + 256] = h[t + 256];
    __syncthreads();
    float p = projb[t];
    const float* w = g_pT + t;
#pragma unroll 4
    for (int k = 0; k < H2; k++) p += hsm[k] * w[(size_t)k * Pn];
    r0s[t] = p * clsW[t];
    r1s[t] = p * clsW[256 + t];
    __syncthreads();
    for (int off = 128; off > 0; off >>= 1) {
        if (t < off) {
            r0s[t] += r0s[t + off];
            r1s[t] += r1s[t + off];
        }
        __syncthreads();
    }
    if (t == 0) {
        float l0 = r0s[0] + clsb[0], l1 = r1s[0] + clsb[1];
        float m = fmaxf(l0, l1);
        float lse = m + logf(expf(l0 - m) + expf(l1 - m));
        out[(c * Bn + b) * 2 + 0] = l0 - lse;
        out[(c * Bn + b) * 2 + 1] = l1 - lse;
    }
}

// ---------------- launch ----------------------------------------------------
extern "C" void kernel_launch(void* const* d_in, const int* in_sizes, int n_in,
                              void* d_out, int out_size) {
    const int*   seq     = (const int*)d_in[0];
    const int*   classes = (const int*)d_in[1];
    const float* embW    = (const float*)d_in[2];
    const float* ecW     = (const float*)d_in[3];
    const float* fWih    = (const float*)d_in[4];
    const float* fWhh    = (const float*)d_in[5];
    const float* fbih    = (const float*)d_in[6];
    const float* fbhh    = (const float*)d_in[7];
    const float* bWih    = (const float*)d_in[8];
    const float* bWhh    = (const float*)d_in[9];
    const float* bbih    = (const float*)d_in[10];
    const float* bbhh    = (const float*)d_in[11];
    const float* dWih    = (const float*)d_in[12];
    const float* dWhh    = (const float*)d_in[13];
    const float* dbih    = (const float*)d_in[14];
    const float* dbhh    = (const float*)d_in[15];
    const float* projW   = (const float*)d_in[16];
    const float* projb   = (const float*)d_in[17];
    const float* clsW    = (const float*)d_in[18];
    const float* clsb    = (const float*)d_in[19];
    float* out = (float*)d_out;

    cudaFuncSetAttribute(lstm2, cudaFuncAttributeMaxDynamicSharedMemorySize,
                         LSTM2_SMEM);

    float *emb_p, *gx_p, *Wc_p, *bc_p, *dT_p, *pT_p;
    cudaGetSymbolAddress((void**)&emb_p, g_emb);
    cudaGetSymbolAddress((void**)&gx_p, g_gx);
    cudaGetSymbolAddress((void**)&Wc_p, g_Wc);
    cudaGetSymbolAddress((void**)&bc_p, g_bc);
    cudaGetSymbolAddress((void**)&dT_p, g_dT);
    cudaGetSymbolAddress((void**)&pT_p, g_pT);

    reset_kernel<<<64, 256>>>();
    embed_kernel<<<Sn * Bn, 128>>>(seq, embW);
    prep_w<<<(Nc * KP + 255) / 256, 256>>>(fWih, bWih, fbih, fbhh, bbih, bbhh);

    dim3 ggrid(Nc / 128, (Sn * Bn) / 128);
    sgemm2<<<ggrid, 256>>>(emb_p, Wc_p, bc_p, gx_p);

    transpose_kernel<<<(G3 * H2 + 255) / 256, 256>>>(dWhh, dT_p, G3, H2);
    transpose_kernel<<<(Pn * H2 + 255) / 256, 256>>>(projW, pT_p, Pn, H2);
    gxd_kernel<<<Cn, 256>>>(classes, ecW, dWih, dbih);

    lstm2<<<128, 256, LSTM2_SMEM>>>(fWhh, bWhh);
    pack_h0<<<(Bn * H2 + 255) / 256, 256>>>();

    for (int c = 0; c < Cn; c++) {
        int sp = c & 1;
        dim3 dgrid(16, 8);
        dec_step1<<<dgrid, 256>>>(c, sp, dbhh);
        dec_step2<<<Bn, 256>>>(c, 1 - sp, projb, clsW, clsb, out);
    }
}